// round 7
// baseline (speedup 1.0000x reference)
#include <cuda_runtime.h>
#include <cuda_bf16.h>
#include <cstdint>

// Conv2d 3x3 s1 p1 NCHW fp32 — implicit GEMM on mma.sync bf16 (m16n8k16),
// 3-pass split precision: AhBh + AhBl + AlBh (al*bl dropped, ~2^-16 rel).
// x: [16,64,224,224]  w: [128,64,3,3]  bias: [128]  out: [16,128,224,224]
// GEMM: M=128 (C_out), N=802816 (spatial), K=576 (=64ci*9tap).
// CTA: 128x128 tile, K in 9 blocks of 64. 256 thr = 8 warps (4M x 2N).
//
// R7: x pre-split to packed bf16 hi|lo (kills convert math in hot loop),
//     B gathers register-staged one block ahead (LDG latency hidden under MMA),
//     A tiles double-buffered via cp.async (issued early, waited after compute).

#define CI_   64
#define CO_   128
#define HDIM  224
#define WDIM  224
#define HW_   (HDIM*WDIM)          // 50176
#define KTOT  576
#define KBLK  64
#define NBLKS 9
#define BN    128
#define BPI   (HW_/BN)             // 392
#define NCTAS (16*BPI)             // 6272
#define XELEMS (16*CI_*HW_)        // 51380224

#define SROW  144                  // padded row stride (bytes), 64 bf16 per row
#define TILE_B (128*SROW)          // 18432
// layout: A0h A0l A1h A1l Bh Bl
#define SMEM_TOTAL (6*TILE_B)      // 110592

__device__ __nv_bfloat16 g_wh[CO_*KTOT];
__device__ __nv_bfloat16 g_wl[CO_*KTOT];
__device__ uint32_t g_xp[XELEMS];   // packed: bf16_hi | bf16_lo << 16

static __device__ __forceinline__ uint32_t smem_u32(const void* p) {
    uint32_t a;
    asm("{ .reg .u64 t; cvta.to.shared.u64 t, %1; cvt.u32.u64 %0, t; }" : "=r"(a) : "l"(p));
    return a;
}
static __device__ __forceinline__ void ldsm_x4(uint32_t* r, uint32_t addr) {
    asm volatile("ldmatrix.sync.aligned.m8n8.x4.shared.b16 {%0,%1,%2,%3}, [%4];"
        : "=r"(r[0]), "=r"(r[1]), "=r"(r[2]), "=r"(r[3]) : "r"(addr));
}
static __device__ __forceinline__ void mma16816(float* c, const uint32_t* a, const uint32_t* b) {
    asm volatile(
        "mma.sync.aligned.m16n8k16.row.col.f32.bf16.bf16.f32 "
        "{%0,%1,%2,%3}, {%4,%5,%6,%7}, {%8,%9}, {%0,%1,%2,%3};"
        : "+f"(c[0]), "+f"(c[1]), "+f"(c[2]), "+f"(c[3])
        : "r"(a[0]), "r"(a[1]), "r"(a[2]), "r"(a[3]), "r"(b[0]), "r"(b[1]));
}
static __device__ __forceinline__ void cp16(uint32_t dst, const void* src) {
    asm volatile("cp.async.cg.shared.global [%0], [%1], 16;" :: "r"(dst), "l"(src));
}
#define CP_COMMIT() asm volatile("cp.async.commit_group;" ::: "memory")
#define CP_WAIT0()  asm volatile("cp.async.wait_group 0;" ::: "memory")

static __device__ __forceinline__ uint32_t pack_split(float v) {
    __nv_bfloat16 h = __float2bfloat16(v);
    __nv_bfloat16 l = __float2bfloat16(v - __bfloat162float(h));
    return (uint32_t)__bfloat16_as_ushort(h) | ((uint32_t)__bfloat16_as_ushort(l) << 16);
}

// ---------------- prologue kernels ----------------
__global__ void conv_prep_w(const float* __restrict__ w) {
    int i = blockIdx.x * 256 + threadIdx.x;
    if (i < CO_ * KTOT) {
        float v = w[i];
        __nv_bfloat16 h = __float2bfloat16(v);
        g_wh[i] = h;
        g_wl[i] = __float2bfloat16(v - __bfloat162float(h));
    }
}
__global__ void conv_prep_x(const float4* __restrict__ x4) {
    int i = blockIdx.x * 256 + threadIdx.x;    // XELEMS/4 = 12845056 iters
    float4 v = x4[i];
    uint4 p;
    p.x = pack_split(v.x); p.y = pack_split(v.y);
    p.z = pack_split(v.z); p.w = pack_split(v.w);
    reinterpret_cast<uint4*>(g_xp)[i] = p;
}

// ---------------- main kernel ----------------
__global__ void __launch_bounds__(256)
conv_mma_kernel(const float* __restrict__ bias,
                float* __restrict__ out) {
    extern __shared__ char smem[];
    char* tBh = smem + 4 * TILE_B;
    char* tBl = smem + 5 * TILE_B;
    const uint32_t sBase = smem_u32(smem);
    const uint32_t sBh = sBase + 4 * TILE_B;
    const uint32_t sBl = sBase + 5 * TILE_B;

    const int tid = threadIdx.x;
    const int wid = tid >> 5;
    const int lid = tid & 31;
    const int warp_m = wid & 3;
    const int warp_n = wid >> 2;

    const int bi    = blockIdx.x;
    const int n_img = bi / BPI;
    const int l0    = (bi - n_img * BPI) * BN;
    const int h0    = l0 / WDIM;
    const int w0    = l0 - h0 * WDIM;
    const uint32_t* xp = g_xp + (size_t)n_img * CI_ * HW_;

    // per-thread B-gather geometry: n fixed, oct = oct0 + it*2
    const int n    = tid & 127;
    const int oct0 = tid >> 7;
    int wc = w0 + n, hh = h0, wp = wc;
    if (wc >= WDIM) { hh = h0 + 1; wp = wc - WDIM; }
    const int base_hw = hh * WDIM + wp;     // add ci*HW + (kh-1)*W + (kw-1)

    // A cp.async geometry
    const int arow  = tid >> 1;
    const int ahalf = tid & 1;

    float acc[16][4];
#pragma unroll
    for (int i = 0; i < 16; ++i)
#pragma unroll
        for (int j = 0; j < 4; ++j) acc[i][j] = 0.0f;

    uint32_t stash[32];

    const int lm = lid >> 3;
    const int lr = lid & 7;

    // ---- helpers as lambdas ----
    auto gatherB = [&](int kblk) {
#pragma unroll
        for (int it = 0; it < 4; ++it) {
            const int oct = oct0 + it * 2;
            int k  = kblk * KBLK + oct * 8;
            int ci = k / 9;
            int r  = k - ci * 9;
            int kh = r / 3;
            int kw = r - kh * 3;
#pragma unroll
            for (int j = 0; j < 8; ++j) {
                const int hi = hh + kh - 1;
                const int wi = wp + kw - 1;
                uint32_t v = 0;
                if ((unsigned)hi < HDIM && (unsigned)wi < WDIM)
                    v = __ldg(xp + ci * HW_ + base_hw + (kh - 1) * WDIM + (kw - 1));
                stash[it * 8 + j] = v;
                if (++kw == 3) { kw = 0; if (++kh == 3) { kh = 0; ++ci; } }
            }
        }
    };
    auto cpasyncA = [&](int kblk, int buf) {
        const uint32_t dA = sBase + buf * 2 * TILE_B
                          + (uint32_t)(arow * SROW + ahalf * 64);
        const __nv_bfloat16* sh = &g_wh[arow * KTOT + kblk * KBLK + ahalf * 32];
        const __nv_bfloat16* sl = &g_wl[arow * KTOT + kblk * KBLK + ahalf * 32];
#pragma unroll
        for (int i = 0; i < 4; ++i) {
            cp16(dA + i * 16,          sh + i * 8);
            cp16(dA + TILE_B + i * 16, sl + i * 8);
        }
        CP_COMMIT();
    };
    auto stsB = [&]() {
#pragma unroll
        for (int it = 0; it < 4; ++it) {
            const int oct = oct0 + it * 2;
            const uint32_t* u = &stash[it * 8];
            uint4 ph, pl;
            ph.x = __byte_perm(u[0], u[1], 0x5410);
            ph.y = __byte_perm(u[2], u[3], 0x5410);
            ph.z = __byte_perm(u[4], u[5], 0x5410);
            ph.w = __byte_perm(u[6], u[7], 0x5410);
            pl.x = __byte_perm(u[0], u[1], 0x7632);
            pl.y = __byte_perm(u[2], u[3], 0x7632);
            pl.z = __byte_perm(u[4], u[5], 0x7632);
            pl.w = __byte_perm(u[6], u[7], 0x7632);
            const int off = n * SROW + oct * 16;
            *reinterpret_cast<uint4*>(tBh + off) = ph;
            *reinterpret_cast<uint4*>(tBl + off) = pl;
        }
    };
    auto compute = [&](int buf) {
        const uint32_t sAh = sBase + buf * 2 * TILE_B;
        const uint32_t sAl = sAh + TILE_B;
#pragma unroll
        for (int ks = 0; ks < 4; ++ks) {
            const int kbyte = ks * 32;
            uint32_t aH[2][4], aL[2][4], bH[8][2], bL[8][2];
#pragma unroll
            for (int mt = 0; mt < 2; ++mt) {
                uint32_t aoff = (uint32_t)((warp_m * 32 + mt * 16 + ((lm & 1) << 3) + lr) * SROW
                                           + kbyte + ((lm >> 1) << 4));
                ldsm_x4(aH[mt], sAh + aoff);
                ldsm_x4(aL[mt], sAl + aoff);
            }
#pragma unroll
            for (int p = 0; p < 4; ++p) {
                uint32_t boff = (uint32_t)((warp_n * 64 + p * 16 + ((lm >> 1) << 3) + lr) * SROW
                                           + kbyte + ((lm & 1) << 4));
                uint32_t rb[4];
                ldsm_x4(rb, sBh + boff);
                bH[2 * p][0] = rb[0]; bH[2 * p][1] = rb[1];
                bH[2 * p + 1][0] = rb[2]; bH[2 * p + 1][1] = rb[3];
                ldsm_x4(rb, sBl + boff);
                bL[2 * p][0] = rb[0]; bL[2 * p][1] = rb[1];
                bL[2 * p + 1][0] = rb[2]; bL[2 * p + 1][1] = rb[3];
            }
#pragma unroll
            for (int mt = 0; mt < 2; ++mt)
#pragma unroll
                for (int nt = 0; nt < 8; ++nt) {
                    float* c = acc[mt * 8 + nt];
                    mma16816(c, aH[mt], bH[nt]);
                    mma16816(c, aH[mt], bL[nt]);
                    mma16816(c, aL[mt], bH[nt]);
                }
        }
    };

    // ---- prologue: stage block 0 ----
    gatherB(0);
    cpasyncA(0, 0);
    stsB();
    CP_WAIT0();
    __syncthreads();

    // ---- main pipeline ----
    for (int b = 0; b < NBLKS; ++b) {
        if (b + 1 < NBLKS) {
            gatherB(b + 1);                 // LDGs in flight during compute
            cpasyncA(b + 1, (b + 1) & 1);   // async into other A buffer
        }
        compute(b & 1);
        __syncthreads();
        if (b + 1 < NBLKS) {
            stsB();                         // consume stash (LDGs landed)
            CP_WAIT0();
            __syncthreads();
        }
    }

    // ---- epilogue ----
    const int qr = lid >> 2;
    const int qc = lid & 3;
#pragma unroll
    for (int mt = 0; mt < 2; ++mt) {
        const int m0 = warp_m * 32 + mt * 16 + qr;
        const float bv0 = __ldg(bias + m0);
        const float bv1 = __ldg(bias + m0 + 8);
        float* r0 = out + ((size_t)n_img * CO_ + m0) * HW_ + l0;
        float* r1 = r0 + 8 * HW_;
#pragma unroll
        for (int nt = 0; nt < 8; ++nt) {
            const float* c = acc[mt * 8 + nt];
            const int col = warp_n * 64 + nt * 8 + qc * 2;
            *reinterpret_cast<float2*>(r0 + col) = make_float2(c[0] + bv0, c[1] + bv0);
            *reinterpret_cast<float2*>(r1 + col) = make_float2(c[2] + bv1, c[3] + bv1);
        }
    }
}

extern "C" void kernel_launch(void* const* d_in, const int* in_sizes, int n_in,
                              void* d_out, int out_size) {
    const float* x    = (const float*)d_in[0];
    const float* w    = (const float*)d_in[1];
    const float* bias = (const float*)d_in[2];
    float* out        = (float*)d_out;

    cudaFuncSetAttribute(conv_mma_kernel,
                         cudaFuncAttributeMaxDynamicSharedMemorySize, SMEM_TOTAL);

    conv_prep_w<<<(CO_ * KTOT + 255) / 256, 256>>>(w);
    conv_prep_x<<<XELEMS / 4 / 256, 256>>>((const float4*)x);
    conv_mma_kernel<<<NCTAS, 256, SMEM_TOTAL>>>(bias, out);
}

// round 9
// speedup vs baseline: 1.3356x; 1.3356x over previous
#include <cuda_runtime.h>
#include <cuda_bf16.h>
#include <cstdint>

// Conv2d 3x3 s1 p1 NCHW fp32 — implicit GEMM on mma.sync bf16 (m16n8k16),
// 3-pass split precision: AhBh + AhBl + AlBh (al*bl dropped, ~2^-16 rel).
// GEMM: M=128 (C_out), N=802816 (spatial), K=576.
// R8: 512 threads / 16 warps (4Mx4N warp grid, 32x32 warp tile) for 2x
// latency hiding; register-stash B prefetch + cp.async A double buffer.

#define CI_   64
#define CO_   128
#define HDIM  224
#define WDIM  224
#define HW_   (HDIM*WDIM)          // 50176
#define KTOT  576
#define KBLK  64
#define NBLKS 9
#define BN    128
#define BPI   (HW_/BN)             // 392
#define NCTAS (16*BPI)             // 6272
#define XELEMS (16*CI_*HW_)        // 51380224
#define NTHR  512

#define SROW  144                  // padded row stride (bytes), 64 bf16 per row
#define TILE_B (128*SROW)          // 18432
// layout: A0h A0l A1h A1l Bh Bl
#define SMEM_TOTAL (6*TILE_B)      // 110592

__device__ __nv_bfloat16 g_wh[CO_*KTOT];
__device__ __nv_bfloat16 g_wl[CO_*KTOT];
__device__ uint32_t g_xp[XELEMS];   // packed: bf16_hi | bf16_lo << 16

static __device__ __forceinline__ uint32_t smem_u32(const void* p) {
    uint32_t a;
    asm("{ .reg .u64 t; cvta.to.shared.u64 t, %1; cvt.u32.u64 %0, t; }" : "=r"(a) : "l"(p));
    return a;
}
static __device__ __forceinline__ void ldsm_x4(uint32_t* r, uint32_t addr) {
    asm volatile("ldmatrix.sync.aligned.m8n8.x4.shared.b16 {%0,%1,%2,%3}, [%4];"
        : "=r"(r[0]), "=r"(r[1]), "=r"(r[2]), "=r"(r[3]) : "r"(addr));
}
static __device__ __forceinline__ void mma16816(float* c, const uint32_t* a, const uint32_t* b) {
    asm volatile(
        "mma.sync.aligned.m16n8k16.row.col.f32.bf16.bf16.f32 "
        "{%0,%1,%2,%3}, {%4,%5,%6,%7}, {%8,%9}, {%0,%1,%2,%3};"
        : "+f"(c[0]), "+f"(c[1]), "+f"(c[2]), "+f"(c[3])
        : "r"(a[0]), "r"(a[1]), "r"(a[2]), "r"(a[3]), "r"(b[0]), "r"(b[1]));
}
static __device__ __forceinline__ void cp16(uint32_t dst, const void* src) {
    asm volatile("cp.async.cg.shared.global [%0], [%1], 16;" :: "r"(dst), "l"(src));
}
#define CP_COMMIT() asm volatile("cp.async.commit_group;" ::: "memory")
#define CP_WAIT0()  asm volatile("cp.async.wait_group 0;" ::: "memory")

static __device__ __forceinline__ uint32_t pack_split(float v) {
    __nv_bfloat16 h = __float2bfloat16(v);
    __nv_bfloat16 l = __float2bfloat16(v - __bfloat162float(h));
    return (uint32_t)__bfloat16_as_ushort(h) | ((uint32_t)__bfloat16_as_ushort(l) << 16);
}

// ---------------- prologue kernels ----------------
__global__ void conv_prep_w(const float* __restrict__ w) {
    int i = blockIdx.x * 256 + threadIdx.x;
    if (i < CO_ * KTOT) {
        float v = w[i];
        __nv_bfloat16 h = __float2bfloat16(v);
        g_wh[i] = h;
        g_wl[i] = __float2bfloat16(v - __bfloat162float(h));
    }
}
__global__ void conv_prep_x(const float4* __restrict__ x4) {
    int i = blockIdx.x * 256 + threadIdx.x;
    float4 v = x4[i];
    uint4 p;
    p.x = pack_split(v.x); p.y = pack_split(v.y);
    p.z = pack_split(v.z); p.w = pack_split(v.w);
    reinterpret_cast<uint4*>(g_xp)[i] = p;
}

// ---------------- main kernel ----------------
__global__ void __launch_bounds__(NTHR)
conv_mma_kernel(const float* __restrict__ bias,
                float* __restrict__ out) {
    extern __shared__ char smem[];
    char* tBh = smem + 4 * TILE_B;
    char* tBl = smem + 5 * TILE_B;
    const uint32_t sBase = smem_u32(smem);
    const uint32_t sBh = sBase + 4 * TILE_B;
    const uint32_t sBl = sBase + 5 * TILE_B;

    const int tid = threadIdx.x;
    const int wid = tid >> 5;
    const int lid = tid & 31;
    const int warp_m = wid & 3;       // 4 warps over M, 32 rows each
    const int warp_n = wid >> 2;      // 4 warps over N, 32 cols each

    const int bi    = blockIdx.x;
    const int n_img = bi / BPI;
    const int l0    = (bi - n_img * BPI) * BN;
    const int h0    = l0 / WDIM;
    const int w0    = l0 - h0 * WDIM;
    const uint32_t* xp = g_xp + (size_t)n_img * CI_ * HW_;

    // B-gather geometry: n fixed per thread, octets grp and grp+4
    const int n   = tid & 127;
    const int grp = tid >> 7;         // 0..3
    int wc = w0 + n, hh = h0, wp = wc;
    if (wc >= WDIM) { hh = h0 + 1; wp = wc - WDIM; }
    const int base_hw = hh * WDIM + wp;

    // A cp.async geometry: row = tid>>2, quarter = tid&3 (32B each)
    const int arow = tid >> 2;
    const int aq   = tid & 3;

    float acc[8][4];
#pragma unroll
    for (int i = 0; i < 8; ++i)
#pragma unroll
        for (int j = 0; j < 4; ++j) acc[i][j] = 0.0f;

    uint32_t stash[16];

    const int lm = lid >> 3;
    const int lr = lid & 7;

    auto gatherB = [&](int kblk) {
#pragma unroll
        for (int it = 0; it < 2; ++it) {
            const int oct = grp + it * 4;
            int k  = kblk * KBLK + oct * 8;
            int ci = k / 9;
            int r  = k - ci * 9;
            int kh = r / 3;
            int kw = r - kh * 3;
#pragma unroll
            for (int j = 0; j < 8; ++j) {
                const int hi = hh + kh - 1;
                const int wi = wp + kw - 1;
                uint32_t v = 0;
                if ((unsigned)hi < HDIM && (unsigned)wi < WDIM)
                    v = __ldg(xp + ci * HW_ + base_hw + (kh - 1) * WDIM + (kw - 1));
                stash[it * 8 + j] = v;
                if (++kw == 3) { kw = 0; if (++kh == 3) { kh = 0; ++ci; } }
            }
        }
    };
    auto cpasyncA = [&](int kblk, int buf) {
        const uint32_t dA = sBase + buf * 2 * TILE_B
                          + (uint32_t)(arow * SROW + aq * 32);
        const __nv_bfloat16* sh = &g_wh[arow * KTOT + kblk * KBLK + aq * 16];
        const __nv_bfloat16* sl = &g_wl[arow * KTOT + kblk * KBLK + aq * 16];
        cp16(dA,               sh);
        cp16(dA + 16,          sh + 8);
        cp16(dA + TILE_B,      sl);
        cp16(dA + TILE_B + 16, sl + 8);
        CP_COMMIT();
    };
    auto stsB = [&]() {
#pragma unroll
        for (int it = 0; it < 2; ++it) {
            const int oct = grp + it * 4;
            const uint32_t* u = &stash[it * 8];
            uint4 ph, pl;
            ph.x = __byte_perm(u[0], u[1], 0x5410);
            ph.y = __byte_perm(u[2], u[3], 0x5410);
            ph.z = __byte_perm(u[4], u[5], 0x5410);
            ph.w = __byte_perm(u[6], u[7], 0x5410);
            pl.x = __byte_perm(u[0], u[1], 0x7632);
            pl.y = __byte_perm(u[2], u[3], 0x7632);
            pl.z = __byte_perm(u[4], u[5], 0x7632);
            pl.w = __byte_perm(u[6], u[7], 0x7632);
            const int off = n * SROW + oct * 16;
            *reinterpret_cast<uint4*>(tBh + off) = ph;
            *reinterpret_cast<uint4*>(tBl + off) = pl;
        }
    };
    auto compute = [&](int buf) {
        const uint32_t sAh = sBase + buf * 2 * TILE_B;
        const uint32_t sAl = sAh + TILE_B;
#pragma unroll
        for (int ks = 0; ks < 4; ++ks) {
            const int kbyte = ks * 32;
            uint32_t aH[2][4], aL[2][4], bH[4][2], bL[4][2];
#pragma unroll
            for (int mt = 0; mt < 2; ++mt) {
                uint32_t aoff = (uint32_t)((warp_m * 32 + mt * 16 + ((lm & 1) << 3) + lr) * SROW
                                           + kbyte + ((lm >> 1) << 4));
                ldsm_x4(aH[mt], sAh + aoff);
                ldsm_x4(aL[mt], sAl + aoff);
            }
#pragma unroll
            for (int p = 0; p < 2; ++p) {
                uint32_t boff = (uint32_t)((warp_n * 32 + p * 16 + ((lm >> 1) << 3) + lr) * SROW
                                           + kbyte + ((lm & 1) << 4));
                uint32_t rb[4];
                ldsm_x4(rb, sBh + boff);
                bH[2 * p][0] = rb[0]; bH[2 * p][1] = rb[1];
                bH[2 * p + 1][0] = rb[2]; bH[2 * p + 1][1] = rb[3];
                ldsm_x4(rb, sBl + boff);
                bL[2 * p][0] = rb[0]; bL[2 * p][1] = rb[1];
                bL[2 * p + 1][0] = rb[2]; bL[2 * p + 1][1] = rb[3];
            }
#pragma unroll
            for (int mt = 0; mt < 2; ++mt)
#pragma unroll
                for (int nt = 0; nt < 4; ++nt) {
                    float* c = acc[mt * 4 + nt];
                    mma16816(c, aH[mt], bH[nt]);
                    mma16816(c, aH[mt], bL[nt]);
                    mma16816(c, aL[mt], bH[nt]);
                }
        }
    };

    // ---- prologue: stage block 0 ----
    gatherB(0);
    cpasyncA(0, 0);
    stsB();
    CP_WAIT0();
    __syncthreads();

    // ---- main pipeline ----
    for (int b = 0; b < NBLKS; ++b) {
        if (b + 1 < NBLKS) {
            gatherB(b + 1);                 // LDGs in flight during compute
            cpasyncA(b + 1, (b + 1) & 1);   // async into other A buffer
        }
        compute(b & 1);
        __syncthreads();
        if (b + 1 < NBLKS) {
            stsB();                         // consume stash (LDGs landed)
            CP_WAIT0();
            __syncthreads();
        }
    }

    // ---- epilogue ----
    const int qr = lid >> 2;
    const int qc = lid & 3;
#pragma unroll
    for (int mt = 0; mt < 2; ++mt) {
        const int m0 = warp_m * 32 + mt * 16 + qr;
        const float bv0 = __ldg(bias + m0);
        const float bv1 = __ldg(bias + m0 + 8);
        float* r0 = out + ((size_t)n_img * CO_ + m0) * HW_ + l0;
        float* r1 = r0 + 8 * HW_;
#pragma unroll
        for (int nt = 0; nt < 4; ++nt) {
            const float* c = acc[mt * 4 + nt];
            const int col = warp_n * 32 + nt * 8 + qc * 2;
            *reinterpret_cast<float2*>(r0 + col) = make_float2(c[0] + bv0, c[1] + bv0);
            *reinterpret_cast<float2*>(r1 + col) = make_float2(c[2] + bv1, c[3] + bv1);
        }
    }
}

extern "C" void kernel_launch(void* const* d_in, const int* in_sizes, int n_in,
                              void* d_out, int out_size) {
    const float* x    = (const float*)d_in[0];
    const float* w    = (const float*)d_in[1];
    const float* bias = (const float*)d_in[2];
    float* out        = (float*)d_out;

    cudaFuncSetAttribute(conv_mma_kernel,
                         cudaFuncAttributeMaxDynamicSharedMemorySize, SMEM_TOTAL);

    conv_prep_w<<<(CO_ * KTOT + 255) / 256, 256>>>(w);
    conv_prep_x<<<XELEMS / 4 / 256, 256>>>((const float4*)x);
    conv_mma_kernel<<<NCTAS, NTHR, SMEM_TOTAL>>>(bias, out);
}